// round 14
// baseline (speedup 1.0000x reference)
#include <cuda_runtime.h>
#include <cuda_bf16.h>

// Problem shape (fixed for this bench problem)
#define SEQ  1024
#define BAT  512
#define NTAG 64
#define TSTRIDE (BAT * NTAG)
#define LN2 0.69314718055994531f

typedef unsigned long long ull;

// Scratch (device globals: allocation-free rule)
__device__ float g_score[BAT];
__device__ float g_v[BAT][NTAG];     // forward half result
__device__ float g_u[BAT][NTAG];     // backward half result
__device__ float g_m0[BAT];
__device__ int   g_esF[BAT];
__device__ int   g_esB[BAT];
__device__ float g_denomG[BAT];      // general-path denominator
__device__ int   g_tick[BAT];
__device__ ull   g_acc;
__device__ int   g_done;
__device__ int   g_maskT[BAT * SEQ];
__device__ int   g_tags_is64;
__device__ int   g_mask_ones;

// ---------------------------------------------------------------------------
__global__ void init_kernel(const int* __restrict__ tags32) {
    const int t = threadIdx.x;
    if (t == 0) {
        int is64 = 1;
        for (int i = 1; i < 128; i += 2)
            if (tags32[i] != 0) { is64 = 0; break; }
        g_tags_is64 = is64;
        g_mask_ones = 1;
        g_acc = 0ull;
        g_done = 0;
    }
    for (int i = t; i < BAT; i += 64) g_tick[i] = 0;
}

__device__ __forceinline__ int load_tag(const void* tags, size_t idx, int is64) {
    if (is64) return (int)((const long long*)tags)[idx];
    return ((const int*)tags)[idx];
}

// ---------------------------------------------------------------------------
__global__ void mask_transpose_kernel(const int* __restrict__ mask) {
    int idx = blockIdx.x * blockDim.x + threadIdx.x;
    if (idx < SEQ * BAT) {
        int t = idx / BAT;
        int b = idx - t * BAT;
        int v = mask[idx];
        g_maskT[b * SEQ + t] = v;
        if (v != 1) g_mask_ones = 0;   // stream-ordered after init
    }
}

// ---------------------------------------------------------------------------
// 64-wide dot in packed f32x2: 16 LDS.128 (broadcast) + 32 FFMA2, 4 accums.
// ---------------------------------------------------------------------------
__device__ __forceinline__ float dot64(const float* __restrict__ rd,
                                       const ull* __restrict__ Ep)
{
    const ulonglong2* s2 = (const ulonglong2*)rd;
    ull a0 = 0ull, a1 = 0ull, a2 = 0ull, a3 = 0ull;
#pragma unroll
    for (int i = 0; i < 16; i += 2) {
        ulonglong2 qA = s2[i];
        ulonglong2 qB = s2[i + 1];
        asm("fma.rn.f32x2 %0, %1, %2, %0;" : "+l"(a0) : "l"(qA.x), "l"(Ep[2 * i + 0]));
        asm("fma.rn.f32x2 %0, %1, %2, %0;" : "+l"(a1) : "l"(qA.y), "l"(Ep[2 * i + 1]));
        asm("fma.rn.f32x2 %0, %1, %2, %0;" : "+l"(a2) : "l"(qB.x), "l"(Ep[2 * i + 2]));
        asm("fma.rn.f32x2 %0, %1, %2, %0;" : "+l"(a3) : "l"(qB.y), "l"(Ep[2 * i + 3]));
    }
    asm("add.rn.f32x2 %0, %0, %1;" : "+l"(a0) : "l"(a2));
    asm("add.rn.f32x2 %0, %0, %1;" : "+l"(a1) : "l"(a3));
    asm("add.rn.f32x2 %0, %0, %1;" : "+l"(a0) : "l"(a1));
    float lo, hi;
    asm("mov.b64 {%0, %1}, %2;" : "=f"(lo), "=f"(hi) : "l"(a0));
    return lo + hi;
}

// ---------------------------------------------------------------------------
// Forward step: snew_j = dot(s, E[:,j]) * exp(logit_j) [* rsc every 4th step]
// ---------------------------------------------------------------------------
template <bool RN>
__device__ __forceinline__ float fstepF(
    const float* __restrict__ rd, float* __restrict__ wr, int j,
    const ull* __restrict__ Ep, float rawv, int& e_sum)
{
    const float c = __expf(rawv);
    float cmul = c;
    if (RN) {
        const float s0 = rd[0];
        int ex = (__float_as_int(s0) >> 23) & 0xFF;
        ex = max(1, min(ex, 253));
        e_sum += ex - 127;
        cmul = c * __int_as_float((254 - ex) << 23);
    }
    const float snew = dot64(rd, Ep) * cmul;
    wr[j] = snew;
    __syncthreads();
    return snew;
}

// ---------------------------------------------------------------------------
// Backward step: u_new_j = dot(u*c, E[j,:]) [* rsc every 4th step]
// ---------------------------------------------------------------------------
template <bool RN>
__device__ __forceinline__ float bstepB(
    float* __restrict__ buf, int j,
    const ull* __restrict__ Ep, float rawv, float u, int& e_sum)
{
    const float c = __expf(rawv);
    buf[j] = u * c;
    __syncthreads();
    float rsc = 1.0f;
    if (RN) {
        const float w0 = buf[0];
        int ex = (__float_as_int(w0) >> 23) & 0xFF;
        ex = max(1, min(ex, 253));
        e_sum += ex - 127;
        rsc = __int_as_float((254 - ex) << 23);
    }
    float r = dot64(buf, Ep);
    return RN ? (r * rsc) : r;
}

// ---------------------------------------------------------------------------
// Combine: executed by ONE full warp of the last-arriving party for batch b.
// Deterministic: fixed-order dot, fixed-point atomic accumulation.
// ---------------------------------------------------------------------------
__device__ void finish(int b, int lane, float* __restrict__ out, int fast) {
    __threadfence();   // acquire: published data visible
    float denom;
    if (fast) {
        float p = g_v[b][lane] * g_u[b][lane]
                + g_v[b][lane + 32] * g_u[b][lane + 32];
#pragma unroll
        for (int o = 16; o > 0; o >>= 1)
            p += __shfl_xor_sync(0xffffffffu, p, o);
        denom = g_m0[b] + (float)(g_esF[b] + g_esB[b]) * LN2 + logf(p);
    } else {
        denom = g_denomG[b];
    }
    const float ll = g_score[b] - denom;
    if (lane == 0) {
        long long q = llrintf(ll * 65536.0f);
        atomicAdd(&g_acc, (ull)q);
        __threadfence();
        int od = atomicAdd(&g_done, 1);
        if (od == BAT - 1) {
            __threadfence();
            long long a = (long long)atomicAdd(&g_acc, 0ull);
            out[0] = (float)((double)a / 65536.0);
        }
    }
}

__device__ __forceinline__ void arrive(int b, int lane, float* __restrict__ out,
                                       int fast) {
    const int K = fast ? 3 : 2;
    int last = 0;
    if (lane == 0) {
        int o = atomicAdd(&g_tick[b], 1);
        last = (o == K - 1);
    }
    last = __shfl_sync(0xffffffffu, last, 0);
    if (last) finish(b, lane, out, fast);
}

// ---------------------------------------------------------------------------
// Split kernel, grid = 2*BAT + BAT/2 blocks of 64 threads, one wave.
//   bid <  BAT      : forward half of batch bid       (fast) / full general
//   bid < 2*BAT     : backward half of batch bid-BAT  (fast only)
//   else            : score block, batches 2*(bid-2*BAT)+warp
// ---------------------------------------------------------------------------
__global__ void __launch_bounds__(64, 10) crf_split_kernel(
    const float* __restrict__ logits,   // [S, B, T]
    const void*  __restrict__ tags,     // [S, B] int32/int64 (detected)
    const float* __restrict__ trans,    // [T, T]
    const float* __restrict__ startt,   // [T]
    const float* __restrict__ endt,     // [T]
    float* __restrict__ out)
{
    const int fast = g_mask_ones;
    const int bid = blockIdx.x;
    const int tid = threadIdx.x;

    // ========================= score blocks =========================
    if (bid >= 2 * BAT) {
        const int w = tid >> 5;
        const int lane = tid & 31;
        const int b = 2 * (bid - 2 * BAT) + w;
        const int is64 = g_tags_is64;
        float s = 0.f;
        if (fast) {
            // mask == all ones: no mask loads, msum = SEQ
            for (int t = lane; t < SEQ - 1; t += 32) {
                const int tg = load_tag(tags, (size_t)t * BAT + b, is64);
                const int tgn = load_tag(tags, (size_t)(t + 1) * BAT + b, is64);
                s += trans[tg * NTAG + tgn];
                s += logits[((size_t)t * BAT + b) * NTAG + tg];
            }
#pragma unroll
            for (int o = 16; o > 0; o >>= 1)
                s += __shfl_xor_sync(0xffffffffu, s, o);
            if (lane == 0) {
                const int last_tag = load_tag(tags, (size_t)(SEQ - 1) * BAT + b, is64);
                const int tg0 = load_tag(tags, (size_t)b, is64);
                g_score[b] = s + startt[tg0] + endt[last_tag]
                           + logits[((size_t)(SEQ - 1) * BAT + b) * NTAG + last_tag];
                __threadfence();
            }
            arrive(b, lane, out, fast);
            return;
        }
        const int* mrow = &g_maskT[b * SEQ];
        int msum = 0;
        for (int t = lane; t < SEQ; t += 32) {
            const int tg = load_tag(tags, (size_t)t * BAT + b, is64);
            const int mt = mrow[t];
            msum += mt;
            if (t < SEQ - 1) {
                const int tgn = load_tag(tags, (size_t)(t + 1) * BAT + b, is64);
                const int mtn = mrow[t + 1];
                s += trans[tg * NTAG + tgn] * (float)mtn;
                s += logits[((size_t)t * BAT + b) * NTAG + tg] * (float)mt;
            }
        }
#pragma unroll
        for (int o = 16; o > 0; o >>= 1) {
            s += __shfl_xor_sync(0xffffffffu, s, o);
            msum += __shfl_xor_sync(0xffffffffu, msum, o);
        }
        if (lane == 0) {
            const int last_idx = msum - 1;
            const int last_tag = load_tag(tags, (size_t)last_idx * BAT + b, is64);
            const int tg0 = load_tag(tags, (size_t)b, is64);
            const float mlast = (float)mrow[SEQ - 1];
            g_score[b] = s + startt[tg0] + endt[last_tag]
                       + logits[((size_t)(SEQ - 1) * BAT + b) * NTAG + last_tag] * mlast;
            __threadfence();
        }
        arrive(b, lane, out, fast);
        return;
    }

    // ========================= chain blocks =========================
    const int isBwd = (bid >= BAT);
    const int b = isBwd ? (bid - BAT) : bid;
    const int j = tid;
    const int w = j >> 5;
    const int l = j & 31;

    __shared__ __align__(16) float se[2][NTAG];
    __shared__ float aux[4];

    if (!fast) {
        // ---- GENERAL PATH: full 1023-step log-space chain, fwd blocks only ----
        if (isBwd) return;   // K = 2: fwd chain + score

        ull Ep[NTAG / 2];
#pragma unroll
        for (int i = 0; i < NTAG / 2; i++) {
            float e0 = __expf(trans[(2 * i) * NTAG + j]);
            float e1 = __expf(trans[(2 * i + 1) * NTAG + j]);
            asm("mov.b64 %0, {%1, %2};" : "=l"(Ep[i]) : "f"(e0), "f"(e1));
        }

        float alpha = startt[j] + logits[(size_t)b * NTAG + j];
        if (j == 0) aux[0] = alpha;
        __syncthreads();
        float m = aux[0];

        const int* mrow = &g_maskT[b * SEQ];
        const float* lptr = logits + (size_t)b * NTAG + j;
        float logit_next = lptr[(size_t)1 * TSTRIDE];

        for (int t = 1; t < SEQ; t++) {
            float* buf = se[t & 1];
            const float logit = logit_next;
            if (t + 1 < SEQ) logit_next = lptr[(size_t)(t + 1) * TSTRIDE];
            const int mk = mrow[t];

            buf[j] = __expf(alpha - m);
            if (j == 0) aux[1] = alpha;
            __syncthreads();

            const float v = dot64(buf, Ep);
            const float na = logit + m + __logf(v);
            alpha = mk ? na : alpha;
            m = aux[1];
            __syncthreads();
        }

        float x = alpha + endt[j];
        float mm = x;
#pragma unroll
        for (int o = 16; o > 0; o >>= 1)
            mm = fmaxf(mm, __shfl_xor_sync(0xffffffffu, mm, o));
        if (l == 0) aux[w] = mm;
        __syncthreads();
        mm = fmaxf(aux[0], aux[1]);
        float e = __expf(x - mm);
#pragma unroll
        for (int o = 16; o > 0; o >>= 1)
            e += __shfl_xor_sync(0xffffffffu, e, o);
        if (l == 0) aux[2 + w] = e;
        __syncthreads();
        if (j == 0) g_denomG[b] = mm + logf(aux[2] + aux[3]);
        __threadfence();
        __syncthreads();
        if (w == 0) arrive(b, l, out, fast);
        return;
    }

    // ========================= FAST PATH =========================
    if (!isBwd) {
        // ---- forward half: v = M_512 ... M_1 s_0 (512 steps) ----
        ull Ep[NTAG / 2];   // E columns packed
#pragma unroll
        for (int i = 0; i < NTAG / 2; i++) {
            float e0 = __expf(trans[(2 * i) * NTAG + j]);
            float e1 = __expf(trans[(2 * i + 1) * NTAG + j]);
            asm("mov.b64 %0, {%1, %2};" : "=l"(Ep[i]) : "f"(e0), "f"(e1));
        }

        const float alpha0 = startt[j] + logits[(size_t)b * NTAG + j];
        if (j == 0) aux[0] = alpha0;
        __syncthreads();
        const float m0 = aux[0];
        float sj = __expf(alpha0 - m0);
        se[0][j] = sj;

        const float* lptr = logits + (size_t)b * NTAG + j;
        float raw[4];
#pragma unroll
        for (int u = 0; u < 4; u++)
            raw[u] = lptr[(size_t)(1 + u) * TSTRIDE];
        __syncthreads();   // se[0] visible

        int esF = 0;
        // 128 groups of 4 (t = 1..512); unconditional prefetch (max t = 516 < 1024)
        const float* pf = lptr + (size_t)5 * TSTRIDE;
        for (int g = 0; g < 128; g++) {
#pragma unroll
            for (int u = 0; u < 4; u++) {
                if (u == 0)
                    sj = fstepF<true >(se[u & 1], se[(u & 1) ^ 1], j, Ep, raw[u], esF);
                else
                    sj = fstepF<false>(se[u & 1], se[(u & 1) ^ 1], j, Ep, raw[u], esF);
                raw[u] = pf[(size_t)u * TSTRIDE];
            }
            pf += (size_t)4 * TSTRIDE;
        }

        g_v[b][j] = sj;
        if (j == 0) { g_m0[b] = m0; g_esF[b] = esF; }
        __threadfence();
        __syncthreads();
        if (w == 0) arrive(b, l, out, fast);
        return;
    } else {
        // ---- backward half: u^T = e_end^T M_1023 ... M_513 (511 steps) ----
        ull Ep[NTAG / 2];   // E ROWS packed
#pragma unroll
        for (int i = 0; i < NTAG / 2; i++) {
            float e0 = __expf(trans[j * NTAG + 2 * i]);
            float e1 = __expf(trans[j * NTAG + 2 * i + 1]);
            asm("mov.b64 %0, {%1, %2};" : "=l"(Ep[i]) : "f"(e0), "f"(e1));
        }

        float u_val = __expf(endt[j]);

        const float* lptr = logits + (size_t)b * NTAG + j;
        float raw[4];
#pragma unroll
        for (int u = 0; u < 4; u++)
            raw[u] = lptr[(size_t)(1023 - u) * TSTRIDE];

        int esB = 0;
        // 127 groups of 4 (k = 0..507, t = 1023-k); unconditional prefetch
        // (min prefetched t = 1023-511 = 512, valid memory)
        const float* pfb = lptr + (size_t)1019 * TSTRIDE;
        for (int g = 0; g < 127; g++) {
#pragma unroll
            for (int u = 0; u < 4; u++) {
                if (u == 0)
                    u_val = bstepB<true >(se[u & 1], j, Ep, raw[u], u_val, esB);
                else
                    u_val = bstepB<false>(se[u & 1], j, Ep, raw[u], u_val, esB);
                raw[u] = pfb[-(long)u * TSTRIDE];
            }
            pfb -= (size_t)4 * TSTRIDE;
        }
        // remainder: k = 508..510 (3 steps, t = 515..513)
#pragma unroll
        for (int u = 0; u < 3; u++) {
            if (u == 0)
                u_val = bstepB<true >(se[u & 1], j, Ep, raw[u], u_val, esB);
            else
                u_val = bstepB<false>(se[u & 1], j, Ep, raw[u], u_val, esB);
        }

        g_u[b][j] = u_val;
        if (j == 0) g_esB[b] = esB;
        __threadfence();
        __syncthreads();
        if (w == 0) arrive(b, l, out, fast);
        return;
    }
}

// ---------------------------------------------------------------------------
extern "C" void kernel_launch(void* const* d_in, const int* in_sizes, int n_in,
                              void* d_out, int out_size) {
    const float* logits = (const float*)d_in[0];   // [S,B,T] f32
    const void*  tags   = d_in[1];                 // [S,B] i32 or i64
    const int*   mask   = (const int*)d_in[2];     // [S,B] i32
    const float* trans  = (const float*)d_in[3];   // [T,T]
    const float* startt = (const float*)d_in[4];   // [T]
    const float* endt   = (const float*)d_in[5];   // [T]
    float* out = (float*)d_out;

    init_kernel<<<1, 64>>>((const int*)tags);
    mask_transpose_kernel<<<(SEQ * BAT + 255) / 256, 256>>>(mask);
    crf_split_kernel<<<2 * BAT + BAT / 2, 64>>>(logits, tags, trans,
                                                startt, endt, out);
}

// round 15
// speedup vs baseline: 1.0120x; 1.0120x over previous
#include <cuda_runtime.h>
#include <cuda_bf16.h>

// Problem shape (fixed for this bench problem)
#define SEQ  1024
#define BAT  512
#define NTAG 64
#define TSTRIDE (BAT * NTAG)
#define LN2 0.69314718055994531f

typedef unsigned long long ull;

// Scratch (device globals: allocation-free rule). All zero-initialized at
// module load; the kernel's finishers restore them to zero every call, so
// CUDA-graph replays see identical initial state.
__device__ float g_score[BAT];
__device__ float g_v[BAT][NTAG];     // forward half result
__device__ float g_u[BAT][NTAG];     // backward half result
__device__ float g_m0[BAT];
__device__ int   g_esF[BAT];
__device__ int   g_esB[BAT];
__device__ float g_denomG[BAT];      // general-path denominator
__device__ int   g_tick[BAT];        // per-batch arrival tickets (reset by finisher)
__device__ ull   g_acc;              // fixed-point sum (reset by global finisher)
__device__ int   g_done;             // batches finished (reset by global finisher)
__device__ int   g_mask_zero;        // set by transpose if any mask!=1 (reset by finisher)
__device__ int   g_maskT[BAT * SEQ];

__device__ __forceinline__ int load_tag(const void* tags, size_t idx, int is64) {
    if (is64) return (int)((const long long*)tags)[idx];
    return ((const int*)tags)[idx];
}

// ---------------------------------------------------------------------------
// Transpose mask [S,B] -> [B,S]; flag any non-1 entry (set-only, benign race).
// ---------------------------------------------------------------------------
__global__ void mask_transpose_kernel(const int* __restrict__ mask) {
    int idx = blockIdx.x * blockDim.x + threadIdx.x;
    if (idx < SEQ * BAT) {
        int t = idx / BAT;
        int b = idx - t * BAT;
        int v = mask[idx];
        g_maskT[b * SEQ + t] = v;
        if (v != 1) g_mask_zero = 1;
    }
}

// ---------------------------------------------------------------------------
// 64-wide dot in packed f32x2: 16 LDS.128 (broadcast) + 32 FFMA2, 4 accums.
// ---------------------------------------------------------------------------
__device__ __forceinline__ float dot64(const float* __restrict__ rd,
                                       const ull* __restrict__ Ep)
{
    const ulonglong2* s2 = (const ulonglong2*)rd;
    ull a0 = 0ull, a1 = 0ull, a2 = 0ull, a3 = 0ull;
#pragma unroll
    for (int i = 0; i < 16; i += 2) {
        ulonglong2 qA = s2[i];
        ulonglong2 qB = s2[i + 1];
        asm("fma.rn.f32x2 %0, %1, %2, %0;" : "+l"(a0) : "l"(qA.x), "l"(Ep[2 * i + 0]));
        asm("fma.rn.f32x2 %0, %1, %2, %0;" : "+l"(a1) : "l"(qA.y), "l"(Ep[2 * i + 1]));
        asm("fma.rn.f32x2 %0, %1, %2, %0;" : "+l"(a2) : "l"(qB.x), "l"(Ep[2 * i + 2]));
        asm("fma.rn.f32x2 %0, %1, %2, %0;" : "+l"(a3) : "l"(qB.y), "l"(Ep[2 * i + 3]));
    }
    asm("add.rn.f32x2 %0, %0, %1;" : "+l"(a0) : "l"(a2));
    asm("add.rn.f32x2 %0, %0, %1;" : "+l"(a1) : "l"(a3));
    asm("add.rn.f32x2 %0, %0, %1;" : "+l"(a0) : "l"(a1));
    float lo, hi;
    asm("mov.b64 {%0, %1}, %2;" : "=f"(lo), "=f"(hi) : "l"(a0));
    return lo + hi;
}

// ---------------------------------------------------------------------------
// Forward step: snew_j = dot(s, E[:,j]) * exp(logit_j) [* rsc every 4th step]
// ---------------------------------------------------------------------------
template <bool RN>
__device__ __forceinline__ float fstepF(
    const float* __restrict__ rd, float* __restrict__ wr, int j,
    const ull* __restrict__ Ep, float rawv, int& e_sum)
{
    const float c = __expf(rawv);
    float cmul = c;
    if (RN) {
        const float s0 = rd[0];
        int ex = (__float_as_int(s0) >> 23) & 0xFF;
        ex = max(1, min(ex, 253));
        e_sum += ex - 127;
        cmul = c * __int_as_float((254 - ex) << 23);
    }
    const float snew = dot64(rd, Ep) * cmul;
    wr[j] = snew;
    __syncthreads();
    return snew;
}

// ---------------------------------------------------------------------------
// Backward step: u_new_j = dot(u*c, E[j,:]) [* rsc every 4th step]
// ---------------------------------------------------------------------------
template <bool RN>
__device__ __forceinline__ float bstepB(
    float* __restrict__ buf, int j,
    const ull* __restrict__ Ep, float rawv, float u, int& e_sum)
{
    const float c = __expf(rawv);
    buf[j] = u * c;
    __syncthreads();
    float rsc = 1.0f;
    if (RN) {
        const float w0 = buf[0];
        int ex = (__float_as_int(w0) >> 23) & 0xFF;
        ex = max(1, min(ex, 253));
        e_sum += ex - 127;
        rsc = __int_as_float((254 - ex) << 23);
    }
    float r = dot64(buf, Ep);
    return RN ? (r * rsc) : r;
}

// ---------------------------------------------------------------------------
// Combine for batch b (one full warp of the last-arriving party).
// Deterministic: fixed-order dot, fixed-point atomic accumulation.
// Also restores the persistent state to zero for the next graph replay.
// ---------------------------------------------------------------------------
__device__ void finish(int b, int lane, float* __restrict__ out, int fast) {
    __threadfence();   // acquire: published data visible
    float denom;
    if (fast) {
        float p = g_v[b][lane] * g_u[b][lane]
                + g_v[b][lane + 32] * g_u[b][lane + 32];
#pragma unroll
        for (int o = 16; o > 0; o >>= 1)
            p += __shfl_xor_sync(0xffffffffu, p, o);
        denom = g_m0[b] + (float)(g_esF[b] + g_esB[b]) * LN2 + logf(p);
    } else {
        denom = g_denomG[b];
    }
    const float ll = g_score[b] - denom;
    if (lane == 0) {
        g_tick[b] = 0;   // reset this batch's ticket for the next replay
        long long q = llrintf(ll * 65536.0f);
        atomicAdd(&g_acc, (ull)q);
        __threadfence();
        int od = atomicAdd(&g_done, 1);
        if (od == BAT - 1) {
            __threadfence();
            long long a = (long long)atomicAdd(&g_acc, 0ull);
            out[0] = (float)((double)a / 65536.0);
            // restore persistent scalars for the next replay
            g_acc = 0ull;
            g_done = 0;
            g_mask_zero = 0;
        }
    }
}

__device__ __forceinline__ void arrive(int b, int lane, float* __restrict__ out,
                                       int fast) {
    const int K = fast ? 3 : 2;
    int last = 0;
    if (lane == 0) {
        int o = atomicAdd(&g_tick[b], 1);
        last = (o == K - 1);
    }
    last = __shfl_sync(0xffffffffu, last, 0);
    if (last) finish(b, lane, out, fast);
}

// ---------------------------------------------------------------------------
// Split kernel, grid = 2*BAT + BAT/2 blocks of 64 threads, one wave.
//   bid <  BAT      : forward half of batch bid       (fast) / full general
//   bid < 2*BAT     : backward half of batch bid-BAT  (fast only)
//   else            : score block, batches 2*(bid-2*BAT)+warp
// ---------------------------------------------------------------------------
__global__ void __launch_bounds__(64, 10) crf_split_kernel(
    const float* __restrict__ logits,   // [S, B, T]
    const void*  __restrict__ tags,     // [S, B] int32/int64 (detected locally)
    const float* __restrict__ trans,    // [T, T]
    const float* __restrict__ startt,   // [T]
    const float* __restrict__ endt,     // [T]
    float* __restrict__ out)
{
    const int fast = (g_mask_zero == 0);
    const int bid = blockIdx.x;
    const int tid = threadIdx.x;

    // ========================= score blocks =========================
    if (bid >= 2 * BAT) {
        const int w = tid >> 5;
        const int lane = tid & 31;
        const int b = 2 * (bid - 2 * BAT) + w;

        // local tags-dtype detection: int64 (little-endian, values<64) has all
        // odd 32-bit words zero; int32 data has random tags there.
        const int probe = ((const int*)tags)[2 * lane + 1];
        const int is64 = (__ballot_sync(0xffffffffu, probe != 0) == 0u);

        float s = 0.f;
        if (fast) {
            // mask == all ones: no mask loads, msum = SEQ
            for (int t = lane; t < SEQ - 1; t += 32) {
                const int tg = load_tag(tags, (size_t)t * BAT + b, is64);
                const int tgn = load_tag(tags, (size_t)(t + 1) * BAT + b, is64);
                s += trans[tg * NTAG + tgn];
                s += logits[((size_t)t * BAT + b) * NTAG + tg];
            }
#pragma unroll
            for (int o = 16; o > 0; o >>= 1)
                s += __shfl_xor_sync(0xffffffffu, s, o);
            if (lane == 0) {
                const int last_tag = load_tag(tags, (size_t)(SEQ - 1) * BAT + b, is64);
                const int tg0 = load_tag(tags, (size_t)b, is64);
                g_score[b] = s + startt[tg0] + endt[last_tag]
                           + logits[((size_t)(SEQ - 1) * BAT + b) * NTAG + last_tag];
                __threadfence();
            }
            arrive(b, lane, out, fast);
            return;
        }
        const int* mrow = &g_maskT[b * SEQ];
        int msum = 0;
        for (int t = lane; t < SEQ; t += 32) {
            const int tg = load_tag(tags, (size_t)t * BAT + b, is64);
            const int mt = mrow[t];
            msum += mt;
            if (t < SEQ - 1) {
                const int tgn = load_tag(tags, (size_t)(t + 1) * BAT + b, is64);
                const int mtn = mrow[t + 1];
                s += trans[tg * NTAG + tgn] * (float)mtn;
                s += logits[((size_t)t * BAT + b) * NTAG + tg] * (float)mt;
            }
        }
#pragma unroll
        for (int o = 16; o > 0; o >>= 1) {
            s += __shfl_xor_sync(0xffffffffu, s, o);
            msum += __shfl_xor_sync(0xffffffffu, msum, o);
        }
        if (lane == 0) {
            const int last_idx = msum - 1;
            const int last_tag = load_tag(tags, (size_t)last_idx * BAT + b, is64);
            const int tg0 = load_tag(tags, (size_t)b, is64);
            const float mlast = (float)mrow[SEQ - 1];
            g_score[b] = s + startt[tg0] + endt[last_tag]
                       + logits[((size_t)(SEQ - 1) * BAT + b) * NTAG + last_tag] * mlast;
            __threadfence();
        }
        arrive(b, lane, out, fast);
        return;
    }

    // ========================= chain blocks =========================
    const int isBwd = (bid >= BAT);
    const int b = isBwd ? (bid - BAT) : bid;
    const int j = tid;
    const int w = j >> 5;
    const int l = j & 31;

    __shared__ __align__(16) float se[2][NTAG];
    __shared__ float aux[4];

    if (!fast) {
        // ---- GENERAL PATH: full 1023-step log-space chain, fwd blocks only ----
        if (isBwd) return;   // K = 2: fwd chain + score

        ull Ep[NTAG / 2];
#pragma unroll
        for (int i = 0; i < NTAG / 2; i++) {
            float e0 = __expf(trans[(2 * i) * NTAG + j]);
            float e1 = __expf(trans[(2 * i + 1) * NTAG + j]);
            asm("mov.b64 %0, {%1, %2};" : "=l"(Ep[i]) : "f"(e0), "f"(e1));
        }

        float alpha = startt[j] + logits[(size_t)b * NTAG + j];
        if (j == 0) aux[0] = alpha;
        __syncthreads();
        float m = aux[0];

        const int* mrow = &g_maskT[b * SEQ];
        const float* lptr = logits + (size_t)b * NTAG + j;
        float logit_next = lptr[(size_t)1 * TSTRIDE];

        for (int t = 1; t < SEQ; t++) {
            float* buf = se[t & 1];
            const float logit = logit_next;
            if (t + 1 < SEQ) logit_next = lptr[(size_t)(t + 1) * TSTRIDE];
            const int mk = mrow[t];

            buf[j] = __expf(alpha - m);
            if (j == 0) aux[1] = alpha;
            __syncthreads();

            const float v = dot64(buf, Ep);
            const float na = logit + m + __logf(v);
            alpha = mk ? na : alpha;
            m = aux[1];
            __syncthreads();
        }

        float x = alpha + endt[j];
        float mm = x;
#pragma unroll
        for (int o = 16; o > 0; o >>= 1)
            mm = fmaxf(mm, __shfl_xor_sync(0xffffffffu, mm, o));
        if (l == 0) aux[w] = mm;
        __syncthreads();
        mm = fmaxf(aux[0], aux[1]);
        float e = __expf(x - mm);
#pragma unroll
        for (int o = 16; o > 0; o >>= 1)
            e += __shfl_xor_sync(0xffffffffu, e, o);
        if (l == 0) aux[2 + w] = e;
        __syncthreads();
        if (j == 0) g_denomG[b] = mm + logf(aux[2] + aux[3]);
        __threadfence();
        __syncthreads();
        if (w == 0) arrive(b, l, out, fast);
        return;
    }

    // ========================= FAST PATH =========================
    if (!isBwd) {
        // ---- forward half: v = M_512 ... M_1 s_0 (512 steps) ----
        ull Ep[NTAG / 2];   // E columns packed
#pragma unroll
        for (int i = 0; i < NTAG / 2; i++) {
            float e0 = __expf(trans[(2 * i) * NTAG + j]);
            float e1 = __expf(trans[(2 * i + 1) * NTAG + j]);
            asm("mov.b64 %0, {%1, %2};" : "=l"(Ep[i]) : "f"(e0), "f"(e1));
        }

        const float alpha0 = startt[j] + logits[(size_t)b * NTAG + j];
        if (j == 0) aux[0] = alpha0;
        __syncthreads();
        const float m0 = aux[0];
        float sj = __expf(alpha0 - m0);
        se[0][j] = sj;

        const float* lptr = logits + (size_t)b * NTAG + j;
        float raw[4];
#pragma unroll
        for (int u = 0; u < 4; u++)
            raw[u] = lptr[(size_t)(1 + u) * TSTRIDE];
        __syncthreads();   // se[0] visible

        int esF = 0;
        // 128 groups of 4 (t = 1..512); unconditional prefetch (max t = 516 < 1024)
        const float* pf = lptr + (size_t)5 * TSTRIDE;
        for (int g = 0; g < 128; g++) {
#pragma unroll
            for (int u = 0; u < 4; u++) {
                if (u == 0)
                    sj = fstepF<true >(se[u & 1], se[(u & 1) ^ 1], j, Ep, raw[u], esF);
                else
                    sj = fstepF<false>(se[u & 1], se[(u & 1) ^ 1], j, Ep, raw[u], esF);
                raw[u] = pf[(size_t)u * TSTRIDE];
            }
            pf += (size_t)4 * TSTRIDE;
        }

        g_v[b][j] = sj;
        if (j == 0) { g_m0[b] = m0; g_esF[b] = esF; }
        __threadfence();
        __syncthreads();
        if (w == 0) arrive(b, l, out, fast);
        return;
    } else {
        // ---- backward half: u^T = e_end^T M_1023 ... M_513 (511 steps) ----
        ull Ep[NTAG / 2];   // E ROWS packed
#pragma unroll
        for (int i = 0; i < NTAG / 2; i++) {
            float e0 = __expf(trans[j * NTAG + 2 * i]);
            float e1 = __expf(trans[j * NTAG + 2 * i + 1]);
            asm("mov.b64 %0, {%1, %2};" : "=l"(Ep[i]) : "f"(e0), "f"(e1));
        }

        float u_val = __expf(endt[j]);

        const float* lptr = logits + (size_t)b * NTAG + j;
        float raw[4];
#pragma unroll
        for (int u = 0; u < 4; u++)
            raw[u] = lptr[(size_t)(1023 - u) * TSTRIDE];

        int esB = 0;
        // 127 groups of 4 (k = 0..507, t = 1023-k); unconditional prefetch
        // (min prefetched t = 1023-511 = 512, valid memory)
        const float* pfb = lptr + (size_t)1019 * TSTRIDE;
        for (int g = 0; g < 127; g++) {
#pragma unroll
            for (int u = 0; u < 4; u++) {
                if (u == 0)
                    u_val = bstepB<true >(se[u & 1], j, Ep, raw[u], u_val, esB);
                else
                    u_val = bstepB<false>(se[u & 1], j, Ep, raw[u], u_val, esB);
                raw[u] = pfb[-(long)u * TSTRIDE];
            }
            pfb -= (size_t)4 * TSTRIDE;
        }
        // remainder: k = 508..510 (3 steps, t = 515..513)
#pragma unroll
        for (int u = 0; u < 3; u++) {
            if (u == 0)
                u_val = bstepB<true >(se[u & 1], j, Ep, raw[u], u_val, esB);
            else
                u_val = bstepB<false>(se[u & 1], j, Ep, raw[u], u_val, esB);
        }

        g_u[b][j] = u_val;
        if (j == 0) g_esB[b] = esB;
        __threadfence();
        __syncthreads();
        if (w == 0) arrive(b, l, out, fast);
        return;
    }
}

// ---------------------------------------------------------------------------
extern "C" void kernel_launch(void* const* d_in, const int* in_sizes, int n_in,
                              void* d_out, int out_size) {
    const float* logits = (const float*)d_in[0];   // [S,B,T] f32
    const void*  tags   = d_in[1];                 // [S,B] i32 or i64
    const int*   mask   = (const int*)d_in[2];     // [S,B] i32
    const float* trans  = (const float*)d_in[3];   // [T,T]
    const float* startt = (const float*)d_in[4];   // [T]
    const float* endt   = (const float*)d_in[5];   // [T]
    float* out = (float*)d_out;

    mask_transpose_kernel<<<(SEQ * BAT + 255) / 256, 256>>>(mask);
    crf_split_kernel<<<2 * BAT + BAT / 2, 64>>>(logits, tags, trans,
                                                startt, endt, out);
}